// round 16
// baseline (speedup 1.0000x reference)
#include <cuda_runtime.h>

#define N_NODES 100000
#define E_EDGES 1600000
#define FIN  16
#define FMID 32
#define FOUT 16
#define CAP  80                            // padded capacity; round16(deg)<=CAP for deg<=CAP
#define ZROW (N_NODES * 16)                // premultiplied index of the all-zero pad row

// ---------------- device scratch ----------------
__device__ int   g_cnt[N_NODES];           // arrival counter (0 at replay start)
__device__ int   g_degc[N_NODES];          // min(deg, CAP) snapshot
__device__ int   g_degp[N_NODES];          // degc rounded up to multiple of 16
__device__ float g_dinv[N_NODES];
__device__ int   g_psrow[N_NODES * CAP];   // padded adjacency, stores r*16 (premultiplied)
__device__ int   g_spill_r[E_EDGES];       // overflow (premultiplied r*16)
__device__ int   g_spill_c[E_EDGES];
__device__ int   g_spill_cursor;           // 0 at replay start
__device__ int   g_spill_n;
__device__ float g_xs [(N_NODES + 1) * FIN];   // x*dinv; last row stays 0 (pad target)
__device__ float g_h2s[(N_NODES + 1) * FOUT];  // (relu(o1)@W2)*dinv; last row stays 0

// ---------------- kernels ----------------

// Fused dtype-detect + padded-CSR build (4 edges/thread, R13 form).
__global__ void k_build(const unsigned int* __restrict__ words,
                        const void* __restrict__ edge_raw, int E) {
    __shared__ unsigned int s_or;
    if (threadIdx.x == 0) s_or = 0u;
    __syncthreads();
    unsigned int accd = words[2 * threadIdx.x + 1] | words[2 * (threadIdx.x + 256) + 1];
    #pragma unroll
    for (int s = 16; s > 0; s >>= 1)
        accd |= __shfl_xor_sync(0xffffffffu, accd, s);
    if ((threadIdx.x & 31) == 0) atomicOr(&s_or, accd);
    __syncthreads();
    const int is64 = (s_or == 0u) ? 1 : 0;

    int base = (blockIdx.x * blockDim.x + threadIdx.x) * 4;
    if (base >= E) return;
    int n = min(4, E - base);

    int r[4], c[4];
    if (n == 4) {
        if (is64) {
            const longlong2* p2 = (const longlong2*)edge_raw;
            longlong2 ra = __ldg(&p2[(base >> 1)]);
            longlong2 rb = __ldg(&p2[(base >> 1) + 1]);
            longlong2 ca = __ldg(&p2[((E + base) >> 1)]);
            longlong2 cb = __ldg(&p2[((E + base) >> 1) + 1]);
            r[0] = (int)ra.x; r[1] = (int)ra.y; r[2] = (int)rb.x; r[3] = (int)rb.y;
            c[0] = (int)ca.x; c[1] = (int)ca.y; c[2] = (int)cb.x; c[3] = (int)cb.y;
        } else {
            const int4* p4 = (const int4*)edge_raw;
            int4 rv = __ldg(&p4[base >> 2]);
            int4 cv = __ldg(&p4[(E + base) >> 2]);
            r[0] = rv.x; r[1] = rv.y; r[2] = rv.z; r[3] = rv.w;
            c[0] = cv.x; c[1] = cv.y; c[2] = cv.z; c[3] = cv.w;
        }
    } else {
        #pragma unroll
        for (int k = 0; k < 4; k++) if (k < n) {
            if (is64) {
                const long long* p = (const long long*)edge_raw;
                r[k] = (int)p[base + k];  c[k] = (int)p[E + base + k];
            } else {
                const int* p = (const int*)edge_raw;
                r[k] = p[base + k];       c[k] = p[E + base + k];
            }
        }
    }
    int rank[4];
    #pragma unroll
    for (int k = 0; k < 4; k++) if (k < n)
        rank[k] = atomicAdd(&g_cnt[c[k]], 1);
    #pragma unroll
    for (int k = 0; k < 4; k++) if (k < n) {
        if (rank[k] < CAP) {
            g_psrow[c[k] * CAP + rank[k]] = r[k] * 16;   // premultiplied
        } else {                                         // correctness fallback
            int s = atomicAdd(&g_spill_cursor, 1);
            g_spill_c[s] = c[k];
            g_spill_r[s] = r[k] * 16;
        }
    }
}

// xs = x*dinv ; degree snapshot/reset ; pad adjacency to multiple of 16 with ZROW.
// 16 lanes per node.
__global__ void k_scale(const float* __restrict__ x) {
    int idx = blockIdx.x * blockDim.x + threadIdx.x;
    if (idx == 0) {
        g_spill_n = g_spill_cursor;
        g_spill_cursor = 0;
    }
    if (idx >= N_NODES * FIN) return;
    int i = idx >> 4;
    int f = idx & 15;
    int deg = g_cnt[i];                     // all 16 lanes read before lane-0 resets
    float d = rsqrtf((float)(deg + 1));     // +1 self-loop
    int degc = min(deg, CAP);
    int degp = min((degc + 15) & ~15, CAP); // multiple of 16 (CAP=80 is too)
    __syncwarp();
    if (f == 0) {
        g_dinv[i] = d;
        g_degc[i] = degc;
        g_degp[i] = degp;
        g_cnt[i]  = 0;                      // ready for next replay
    }
    if (degc + f < degp)                    // pad (<=15 entries, one per lane)
        g_psrow[i * CAP + degc + f] = ZROW;
    g_xs[idx] = __ldg(&x[idx]) * d;
}

// Fused gather1 + W1 + relu + W2. WARP per node: lane = es*16 + f.
// Padded trip count -> fully unrolled 16-edge blocks, no divergence, no tail.
__global__ void k_gather1_lin12(const float* __restrict__ W1,
                                const float* __restrict__ b1,
                                const float* __restrict__ W2) {
    __shared__ float sW1[FIN * FMID];
    __shared__ float sW2[FMID * FOUT];
    __shared__ float sb1[FMID];
    __shared__ float sagg[8][FIN];
    __shared__ float so1[8][FMID];
    for (int t = threadIdx.x; t < FIN * FMID; t += blockDim.x) {
        sW1[t] = W1[t];
        sW2[t] = W2[t];
    }
    for (int t = threadIdx.x; t < FMID; t += blockDim.x) sb1[t] = b1[t];
    __syncthreads();

    int w = (blockIdx.x * blockDim.x + threadIdx.x) >> 5;   // node (grid exact)
    int lane = threadIdx.x & 31;
    int f  = lane & 15;
    int es = lane >> 4;                     // edge slot 0/1
    int h  = (threadIdx.x >> 5) & 7;        // warp slot in block

    const int* adj = &g_psrow[w * CAP];
    int degp = g_degp[w];
    float d = g_dinv[w];

    float acc = (es == 0) ? g_xs[w * FIN + f] : 0.0f;       // self-loop on slot 0
    for (int j = 0; j < degp; j += 16) {
        #pragma unroll
        for (int u = 0; u < 8; u++) {
            int rx = __ldg(&adj[j + 2 * u + es]);           // broadcast per half
            acc += __ldg(&g_xs[rx + f]);
        }
    }
    if (es == 0) {                          // spill path (sn == 0 for this input)
        int sn = g_spill_n;
        for (int i = 0; i < sn; i++)
            if (g_spill_c[i] == w)
                acc += __ldg(&g_xs[g_spill_r[i] + f]);
    }
    acc += __shfl_xor_sync(0xffffffffu, acc, 16);           // merge slots
    if (es == 0) sagg[h][f] = acc;
    __syncwarp();

    // mid = agg @ W1 : one lane per mid feature (32 lanes)
    {
        float m = 0.0f;
        #pragma unroll
        for (int k = 0; k < FIN; k++)
            m = fmaf(sagg[h][k], sW1[k * FMID + lane], m);
        so1[h][lane] = fmaxf(fmaf(m, d, sb1[lane]), 0.0f);
    }
    __syncwarp();
    if (lane < FOUT) {
        float s = 0.0f;
        #pragma unroll
        for (int k = 0; k < FMID; k++)
            s = fmaf(so1[h][k], sW2[k * FOUT + lane], s);
        g_h2s[w * FOUT + lane] = s * d;
    }
}

// Fused gather2 + final. WARP per node: lane = es*16 + f. Padded, divergence-free.
__global__ void k_gather2_final(const float* __restrict__ fcW,
                                const float* __restrict__ fcb,
                                const float* __restrict__ b2,
                                float* __restrict__ out) {
    int w = (blockIdx.x * blockDim.x + threadIdx.x) >> 5;
    if (w >= N_NODES) return;
    int lane = threadIdx.x & 31;
    int f  = lane & 15;
    int es = lane >> 4;

    const int* adj = &g_psrow[w * CAP];
    int degp = g_degp[w];

    float acc = (es == 0) ? __ldg(&g_h2s[w * FOUT + f]) : 0.0f;  // self-loop
    for (int j = 0; j < degp; j += 16) {
        #pragma unroll
        for (int u = 0; u < 8; u++) {
            int rx = __ldg(&adj[j + 2 * u + es]);
            acc += __ldg(&g_h2s[rx + f]);
        }
    }
    if (es == 0) {
        int sn = g_spill_n;
        for (int i = 0; i < sn; i++)
            if (g_spill_c[i] == w)
                acc += __ldg(&g_h2s[g_spill_r[i] + f]);
    }
    acc += __shfl_xor_sync(0xffffffffu, acc, 16);

    float d = g_dinv[w];
    float v = fmaxf(fmaf(acc, d, __ldg(&b2[f])), 0.0f) * __ldg(&fcW[f]);
    #pragma unroll
    for (int s = 8; s > 0; s >>= 1)
        v += __shfl_xor_sync(0xffffffffu, v, s, 16);
    if (lane == 0) out[w] = v + __ldg(&fcb[0]);
}

// ---------------- launch ----------------
extern "C" void kernel_launch(void* const* d_in, const int* in_sizes, int n_in,
                              void* d_out, int out_size) {
    const void*  edge = d_in[0];
    const float* x    = (const float*)d_in[1];
    const float* W1   = (const float*)d_in[2];
    const float* b1   = (const float*)d_in[3];
    const float* W2   = (const float*)d_in[4];
    const float* b2   = (const float*)d_in[5];
    const float* fcW  = (const float*)d_in[6];
    const float* fcb  = (const float*)d_in[7];
    float* out = (float*)d_out;

    const int E = in_sizes[0] / 2;
    const int T = 256;

    k_build         <<<(E / 4 + T - 1) / T, T>>>((const unsigned int*)edge, edge, E);
    k_scale         <<<(N_NODES * FIN + T - 1) / T, T>>>(x);
    k_gather1_lin12 <<<(N_NODES * 32 + T - 1) / T, T>>>(W1, b1, W2);
    k_gather2_final <<<(N_NODES * 32 + T - 1) / T, T>>>(fcW, fcb, b2, out);
}

// round 17
// speedup vs baseline: 1.1421x; 1.1421x over previous
#include <cuda_runtime.h>

#define N_NODES 100000
#define E_EDGES 1600000
#define FIN  16
#define FMID 32
#define FOUT 16
#define CAP  64                            // padded per-node capacity (mean deg 16)
#define SBLK 1024                          // nodes per sort block

// ---------------- device scratch ----------------
__device__ int   g_cnt[N_NODES];           // arrival counter (0 at replay start)
__device__ int   g_degc[N_NODES];          // min(deg, CAP) snapshot
__device__ float g_dinv[N_NODES];
__device__ int   g_perm[N_NODES];          // degree-sorted node order (per 1024-block)
__device__ int   g_psrow[N_NODES * CAP];   // padded adjacency, stores r*16 (premultiplied)
__device__ int   g_spill_r[E_EDGES];       // overflow (premultiplied r*16)
__device__ int   g_spill_c[E_EDGES];
__device__ int   g_spill_cursor;           // 0 at replay start
__device__ int   g_spill_n;
__device__ float g_xs [N_NODES * FIN];     // x * dinv  (layer-1 gather source, 64B rows)
__device__ float g_h2s[N_NODES * FOUT];    // (relu(o1) @ W2) * dinv

// ---------------- kernels ----------------

// Fused dtype-detect + padded-CSR build (4 edges/thread — best measured form).
__global__ void k_build(const unsigned int* __restrict__ words,
                        const void* __restrict__ edge_raw, int E) {
    __shared__ unsigned int s_or;
    if (threadIdx.x == 0) s_or = 0u;
    __syncthreads();
    unsigned int accd = words[2 * threadIdx.x + 1] | words[2 * (threadIdx.x + 256) + 1];
    #pragma unroll
    for (int s = 16; s > 0; s >>= 1)
        accd |= __shfl_xor_sync(0xffffffffu, accd, s);
    if ((threadIdx.x & 31) == 0) atomicOr(&s_or, accd);
    __syncthreads();
    const int is64 = (s_or == 0u) ? 1 : 0;

    int base = (blockIdx.x * blockDim.x + threadIdx.x) * 4;
    if (base >= E) return;
    int n = min(4, E - base);

    int r[4], c[4];
    if (n == 4) {
        if (is64) {
            const longlong2* p2 = (const longlong2*)edge_raw;
            longlong2 ra = __ldg(&p2[(base >> 1)]);
            longlong2 rb = __ldg(&p2[(base >> 1) + 1]);
            longlong2 ca = __ldg(&p2[((E + base) >> 1)]);
            longlong2 cb = __ldg(&p2[((E + base) >> 1) + 1]);
            r[0] = (int)ra.x; r[1] = (int)ra.y; r[2] = (int)rb.x; r[3] = (int)rb.y;
            c[0] = (int)ca.x; c[1] = (int)ca.y; c[2] = (int)cb.x; c[3] = (int)cb.y;
        } else {
            const int4* p4 = (const int4*)edge_raw;
            int4 rv = __ldg(&p4[base >> 2]);
            int4 cv = __ldg(&p4[(E + base) >> 2]);
            r[0] = rv.x; r[1] = rv.y; r[2] = rv.z; r[3] = rv.w;
            c[0] = cv.x; c[1] = cv.y; c[2] = cv.z; c[3] = cv.w;
        }
    } else {
        #pragma unroll
        for (int k = 0; k < 4; k++) if (k < n) {
            if (is64) {
                const long long* p = (const long long*)edge_raw;
                r[k] = (int)p[base + k];  c[k] = (int)p[E + base + k];
            } else {
                const int* p = (const int*)edge_raw;
                r[k] = p[base + k];       c[k] = p[E + base + k];
            }
        }
    }
    int rank[4];
    #pragma unroll
    for (int k = 0; k < 4; k++) if (k < n)
        rank[k] = atomicAdd(&g_cnt[c[k]], 1);
    #pragma unroll
    for (int k = 0; k < 4; k++) if (k < n) {
        if (rank[k] < CAP) {
            g_psrow[c[k] * CAP + rank[k]] = r[k] * 16;   // premultiplied
        } else {                                         // correctness fallback
            int s = atomicAdd(&g_spill_cursor, 1);
            g_spill_c[s] = c[k];
            g_spill_r[s] = r[k] * 16;
        }
    }
}

// dinv + counter snapshot/reset + per-1024-block degree counting-sort (g_perm)
// + xs = x*dinv. One thread per node for the sort part.
__global__ void __launch_bounds__(SBLK)
k_scale_sort(const float* __restrict__ x) {
    __shared__ int   s_cnt[CAP + 1];        // exact-degc bins 0..CAP
    __shared__ float s_dinv[SBLK];

    int base = blockIdx.x * SBLK;
    int t = base + threadIdx.x;
    bool valid = (t < N_NODES);

    if (threadIdx.x <= CAP) s_cnt[threadIdx.x] = 0;
    __syncthreads();

    int degc = 0;
    float d = 1.0f;
    if (valid) {
        int deg = g_cnt[t];
        d = rsqrtf((float)(deg + 1));       // +1 self-loop
        degc = min(deg, CAP);
        g_dinv[t] = d;
        g_degc[t] = degc;
        g_cnt[t]  = 0;                      // ready for next replay
        atomicAdd(&s_cnt[degc], 1);
    }
    s_dinv[threadIdx.x] = d;
    if (t == 0) {
        g_spill_n = g_spill_cursor;
        g_spill_cursor = 0;
    }
    __syncthreads();
    if (threadIdx.x == 0) {                 // exclusive prefix over 65 bins
        int run = 0;
        #pragma unroll
        for (int i = 0; i <= CAP; i++) { int v = s_cnt[i]; s_cnt[i] = run; run += v; }
    }
    __syncthreads();
    if (valid) {
        int slot = atomicAdd(&s_cnt[degc], 1);   // local rank in degree order
        g_perm[base + slot] = t;
    }

    // xs = x * dinv for this block's nodes (coalesced)
    int nblk = min(SBLK, N_NODES - base);
    for (int i = threadIdx.x; i < nblk * FIN; i += SBLK) {
        int nl = i >> 4;
        g_xs[base * FIN + i] = __ldg(&x[base * FIN + i]) * s_dinv[nl];
    }
}

// Fused gather1 + W1 + relu + W2 (input-space aggregation), R13 layout,
// processing nodes in degree-sorted order: w = perm[slot].
__global__ void k_gather1_lin12(const float* __restrict__ W1,
                                const float* __restrict__ b1,
                                const float* __restrict__ W2) {
    __shared__ float sW1[FIN * FMID];
    __shared__ float sW2[FMID * FOUT];
    __shared__ float sb1[FMID];
    __shared__ float sagg[16][FIN];
    __shared__ float so1[16][FMID];
    for (int t = threadIdx.x; t < FIN * FMID; t += blockDim.x) {
        sW1[t] = W1[t];
        sW2[t] = W2[t];
    }
    for (int t = threadIdx.x; t < FMID; t += blockDim.x) sb1[t] = b1[t];
    __syncthreads();

    int slot = (blockIdx.x * blockDim.x + threadIdx.x) >> 4;   // grid exact
    int f = threadIdx.x & 15;
    int h = (threadIdx.x >> 4) & 15;
    int w = __ldg(&g_perm[slot]);

    const int4* adj4 = (const int4*)&g_psrow[w * CAP];
    int deg = g_degc[w];
    float d = g_dinv[w];

    float acc0 = g_xs[w * FIN + f];         // self-loop
    float acc1 = 0.0f;
    int j = 0;
    for (; j + 8 <= deg; j += 8) {
        int4 ia = __ldg(&adj4[j >> 2]);
        int4 ib = __ldg(&adj4[(j >> 2) + 1]);
        float a0 = __ldg(&g_xs[ia.x + f]);
        float a1 = __ldg(&g_xs[ia.y + f]);
        float a2 = __ldg(&g_xs[ia.z + f]);
        float a3 = __ldg(&g_xs[ia.w + f]);
        float a4 = __ldg(&g_xs[ib.x + f]);
        float a5 = __ldg(&g_xs[ib.y + f]);
        float a6 = __ldg(&g_xs[ib.z + f]);
        float a7 = __ldg(&g_xs[ib.w + f]);
        acc0 += (a0 + a1) + (a2 + a3);
        acc1 += (a4 + a5) + (a6 + a7);
    }
    for (; j < deg; j++)
        acc0 += __ldg(&g_xs[g_psrow[w * CAP + j] + f]);
    float acc = acc0 + acc1;

    int sn = g_spill_n;                     // 0 for this input; correctness path
    for (int i = 0; i < sn; i++)
        if (g_spill_c[i] == w)
            acc += __ldg(&g_xs[g_spill_r[i] + f]);

    sagg[h][f] = acc;
    __syncthreads();

    {
        float m0 = 0.0f, m1 = 0.0f;
        #pragma unroll
        for (int k = 0; k < FIN; k++) {
            float a = sagg[h][k];
            m0 = fmaf(a, sW1[k * FMID + f],      m0);
            m1 = fmaf(a, sW1[k * FMID + f + 16], m1);
        }
        so1[h][f]      = fmaxf(fmaf(m0, d, sb1[f]),      0.0f);
        so1[h][f + 16] = fmaxf(fmaf(m1, d, sb1[f + 16]), 0.0f);
    }
    __syncthreads();

    {
        float s = 0.0f;
        #pragma unroll
        for (int k = 0; k < FMID; k++)
            s = fmaf(so1[h][k], sW2[k * FOUT + f], s);
        g_h2s[w * FOUT + f] = s * d;
    }
}

// Fused gather2 + final, degree-sorted order.
__global__ void k_gather2_final(const float* __restrict__ fcW,
                                const float* __restrict__ fcb,
                                const float* __restrict__ b2,
                                float* __restrict__ out) {
    int slot = (blockIdx.x * blockDim.x + threadIdx.x) >> 4;
    if (slot >= N_NODES) return;
    int f = threadIdx.x & 15;
    int w = __ldg(&g_perm[slot]);

    const int4* adj4 = (const int4*)&g_psrow[w * CAP];
    int deg = g_degc[w];
    float acc0 = __ldg(&g_h2s[w * FOUT + f]);   // self-loop
    float acc1 = 0.0f;
    int j = 0;
    for (; j + 8 <= deg; j += 8) {
        int4 ia = __ldg(&adj4[j >> 2]);
        int4 ib = __ldg(&adj4[(j >> 2) + 1]);
        float a0 = __ldg(&g_h2s[ia.x + f]);
        float a1 = __ldg(&g_h2s[ia.y + f]);
        float a2 = __ldg(&g_h2s[ia.z + f]);
        float a3 = __ldg(&g_h2s[ia.w + f]);
        float a4 = __ldg(&g_h2s[ib.x + f]);
        float a5 = __ldg(&g_h2s[ib.y + f]);
        float a6 = __ldg(&g_h2s[ib.z + f]);
        float a7 = __ldg(&g_h2s[ib.w + f]);
        acc0 += (a0 + a1) + (a2 + a3);
        acc1 += (a4 + a5) + (a6 + a7);
    }
    for (; j < deg; j++)
        acc0 += __ldg(&g_h2s[g_psrow[w * CAP + j] + f]);
    float acc = acc0 + acc1;

    int sn = g_spill_n;
    for (int i = 0; i < sn; i++)
        if (g_spill_c[i] == w)
            acc += __ldg(&g_h2s[g_spill_r[i] + f]);

    float d = g_dinv[w];
    float v = fmaxf(fmaf(acc, d, __ldg(&b2[f])), 0.0f) * __ldg(&fcW[f]);
    #pragma unroll
    for (int s = 8; s > 0; s >>= 1)
        v += __shfl_xor_sync(0xffffffffu, v, s, 16);
    if (f == 0) out[w] = v + __ldg(&fcb[0]);
}

// ---------------- launch ----------------
extern "C" void kernel_launch(void* const* d_in, const int* in_sizes, int n_in,
                              void* d_out, int out_size) {
    const void*  edge = d_in[0];
    const float* x    = (const float*)d_in[1];
    const float* W1   = (const float*)d_in[2];
    const float* b1   = (const float*)d_in[3];
    const float* W2   = (const float*)d_in[4];
    const float* b2   = (const float*)d_in[5];
    const float* fcW  = (const float*)d_in[6];
    const float* fcb  = (const float*)d_in[7];
    float* out = (float*)d_out;

    const int E = in_sizes[0] / 2;
    const int T = 256;

    k_build        <<<(E / 4 + T - 1) / T, T>>>((const unsigned int*)edge, edge, E);
    k_scale_sort   <<<(N_NODES + SBLK - 1) / SBLK, SBLK>>>(x);
    k_gather1_lin12<<<(N_NODES * FIN + T - 1) / T, T>>>(W1, b1, W2);
    k_gather2_final<<<(N_NODES * FOUT + T - 1) / T, T>>>(fcW, fcb, b2, out);
}